// round 10
// baseline (speedup 1.0000x reference)
#include <cuda_runtime.h>
#include <cuda_fp16.h>
#include <cstdint>

// Conv2D 3x3 s1 p1: x[8,16,512,512] fp32 * w[16,144] -> out[8,16,512,512]
// Implicit GEMM on mma.sync.m16n8k16 (f16, f32 acc), persistent CTAs.
// R10: staging via cp.async.bulk (one 160B op per (ci,row), 288/tile) with
// mbarrier completion — removes the 2304x LDGSTS 8-cyc issue tax that capped
// R5-R9 at ~100us. Edge handling: clamped sources, OOB zeroed in cvt.
// CTA tile: 32(x) x 16(y), all 16 co, 8 warps. 2 CTAs/SM.

#define HW      512
#define NSX     34
#define NSY     18
#define CPAD    24       // ci stride (halves): 48B rows, LDSM conflict-free
#define RAWROW  40       // raw row: 40 floats = 160B, col c <-> gx = x0-4+c
#define NTILES  4096
#define GRID    304      // 2 CTAs/SM x 152 SMs

#define RAW_OFF  0                         // 16*18*160 = 46080 B
#define NS_OFF   46080                     // 18*34*24*2 = 29376 B
#define BS_OFF   75456                     // 18*32*8 = 4608 B
#define MBAR_OFF 80064
#define SM_TOTAL 80072

static __device__ __forceinline__ void mma16816(float* c, uint32_t a0, uint32_t a1,
                                                uint32_t a2, uint32_t a3,
                                                uint32_t b0, uint32_t b1) {
    asm volatile(
        "mma.sync.aligned.m16n8k16.row.col.f32.f16.f16.f32 "
        "{%0,%1,%2,%3}, {%4,%5,%6,%7}, {%8,%9}, {%0,%1,%2,%3};"
        : "+f"(c[0]), "+f"(c[1]), "+f"(c[2]), "+f"(c[3])
        : "r"(a0), "r"(a1), "r"(a2), "r"(a3), "r"(b0), "r"(b1));
}

static __device__ __forceinline__ void ldsm4(uint32_t& a0, uint32_t& a1,
                                             uint32_t& a2, uint32_t& a3, uint32_t addr) {
    asm volatile("ldmatrix.sync.aligned.m8n8.x4.shared.b16 {%0,%1,%2,%3}, [%4];"
                 : "=r"(a0), "=r"(a1), "=r"(a2), "=r"(a3) : "r"(addr));
}

static __device__ __forceinline__ void bulk_g2s(uint32_t dst, const float* src,
                                                uint32_t bytes, uint32_t mbar) {
    asm volatile(
        "cp.async.bulk.shared::cluster.global.mbarrier::complete_tx::bytes "
        "[%0], [%1], %2, [%3];"
        :: "r"(dst), "l"(src), "r"(bytes), "r"(mbar) : "memory");
}

static __device__ __forceinline__ uint32_t smem_u32(const void* p) {
    uint32_t a;
    asm("{ .reg .u64 t; cvta.to.shared.u64 t, %1; cvt.u32.u64 %0, t; }" : "=r"(a) : "l"(p));
    return a;
}

static __device__ __forceinline__ void mbar_wait(uint32_t mbar, uint32_t parity) {
    uint32_t done;
    asm volatile(
        "{\n\t.reg .pred p;\n\t"
        "mbarrier.try_wait.parity.acquire.cta.shared::cta.b64 p, [%1], %2;\n\t"
        "selp.b32 %0, 1, 0, p;\n\t}"
        : "=r"(done) : "r"(mbar), "r"(parity) : "memory");
    if (!done) {
        asm volatile(
            "{\n\t.reg .pred P1;\n\tWL_%=: \n\t"
            "mbarrier.try_wait.parity.acquire.cta.shared::cta.b64 P1, [%0], %1, 0x989680;\n\t"
            "@P1 bra.uni WD_%=;\n\tbra.uni WL_%=;\n\tWD_%=: \n\t}"
            :: "r"(mbar), "r"(parity) : "memory");
    }
}

// Per-tile transfer size per row (uniform within a tile).
static __device__ __forceinline__ uint32_t row_bytes(int x0) {
    return (x0 == 0 || x0 == 480) ? 144u : 160u;
}

// Issue this thread's share (1-2 rows) of the tile's 288 bulk ops.
static __device__ __forceinline__ void issue_tile_bulk(const float* __restrict__ xin,
                                                       uint32_t sraw, uint32_t mbar,
                                                       int tile, int ci, int xb) {
    const int x0 = (tile & 15) * 32, y0 = ((tile >> 4) & 31) * 16, n = tile >> 9;
    const bool le = (x0 == 0);
    const int  srcx = le ? 0 : (x0 - 4);
    const uint32_t dsh = le ? 16u : 0u;          // keeps col c <-> gx = x0-4+c identity
    const uint32_t sz  = row_bytes(x0);
    const float* src = xin + (size_t)(n * 16 + ci) * HW * HW + srcx;
    const uint32_t dbase = sraw + (uint32_t)(ci * NSY * RAWROW) * 4 + dsh;

    #pragma unroll
    for (int s = 0; s < 2; ++s) {
        const int r = xb + 16 * s;
        if (r < NSY) {
            int gy = y0 + r - 1;
            gy = gy < 0 ? 0 : (gy > HW - 1 ? HW - 1 : gy);   // clamp; cvt zeroes OOB
            bulk_g2s(dbase + (uint32_t)(r * RAWROW) * 4, src + (size_t)gy * HW, sz, mbar);
        }
    }
}

__global__ __launch_bounds__(256, 2)
void conv_mma_bulk(const float* __restrict__ xin,
                   const float* __restrict__ wgt,
                   float* __restrict__ out)
{
    extern __shared__ __align__(16) char smem[];
    float*  raw = (float*)(smem + RAW_OFF);
    __half* ns  = (__half*)(smem + NS_OFF);
    uint2*  Bs2 = (uint2*)(smem + BS_OFF);
    const uint32_t sraw = smem_u32(smem) + RAW_OFF;
    const uint32_t nsu  = smem_u32(smem) + NS_OFF;
    const uint32_t mbar = smem_u32(smem) + MBAR_OFF;

    const int t    = threadIdx.x;
    const int lane = t & 31;
    const int wrp  = t >> 5;
    const int ci   = t >> 4;     // bulk-issue mapping
    const int xb   = t & 15;

    // ---- stage weights once: Bs2[slot=(dy*3+kw)*2+nn][lane] = {b0,b1} ----
    #pragma unroll
    for (int e = t; e < 576; e += 256) {
        const int slot = e >> 5, l2 = e & 31;
        const int g2 = l2 >> 2, cq2 = (l2 & 3) * 2;
        const int nn = slot & 1, kwk = (slot >> 1) % 3, dy = slot / 6;
        const float* wb = wgt + (nn * 8 + g2) * 144 + dy * 3 + kwk;
        __half2 w0 = __floats2half2_rn(wb[cq2 * 9],       wb[(cq2 + 1) * 9]);
        __half2 w1 = __floats2half2_rn(wb[(cq2 + 8) * 9], wb[(cq2 + 9) * 9]);
        uint2 v;
        v.x = *(const uint32_t*)&w0;
        v.y = *(const uint32_t*)&w1;
        Bs2[e] = v;
    }

    const int g  = lane >> 2;
    const int cq = (lane & 3) * 2;
    const uint32_t fb = nsu + (uint32_t)(((lane & 15) * CPAD + (lane >> 4) * 8) * 2);

    // cvt mapping: ci pair = wrp, lane = ns x-column xx; raw col = xx + 3
    const float* cr0 = raw + (2 * wrp) * (NSY * RAWROW);
    const float* cr1 = cr0 + NSY * RAWROW;
    const int colA = lane + 3;           // ns xx = lane        (gx = x0 + lane - 1)
    const int colB = 32 + lane + 3;      // ns xx = 32 + lane   (lane < 2)

    // ---- prologue: init mbar, expect + issue tile0 ----
    const int tile0 = blockIdx.x;
    if (t == 0) {
        asm volatile("mbarrier.init.shared.b64 [%0], 1;" :: "r"(mbar) : "memory");
        const uint32_t bytes0 = 288u * row_bytes((tile0 & 15) * 32);
        asm volatile("mbarrier.arrive.expect_tx.shared.b64 _, [%0], %1;"
                     :: "r"(mbar), "r"(bytes0) : "memory");
    }
    __syncthreads();
    issue_tile_bulk(xin, sraw, mbar, tile0, ci, xb);

    uint32_t ph = 0;
    for (int tile = tile0; tile < NTILES; tile += GRID) {
        const int x0 = (tile & 15) * 32, y0 = ((tile >> 4) & 31) * 16, n = tile >> 9;
        const bool pA = !(lane == 0 && x0 == 0);         // gx = x0-1 at left image edge
        const bool pB = !(lane == 1 && x0 == 480);       // gx = 512 at right image edge

        // ---- wait raw(k) (transfer issued one compute-phase ago -> hidden) ----
        mbar_wait(mbar, ph);
        ph ^= 1;
        __syncthreads();                 // prev compute done -> ns writable

        // ---- cvt raw fp32 -> ns fp16 (zero OOB here; loader just clamps) ----
        #pragma unroll 3
        for (int yy = 0; yy < NSY; ++yy) {
            const int gy = y0 + yy - 1;
            const bool okY = (unsigned)gy < HW;
            const int ro = yy * RAWROW;
            float a0 = (okY && pA) ? cr0[ro + colA] : 0.0f;
            float a1 = (okY && pA) ? cr1[ro + colA] : 0.0f;
            *(__half2*)&ns[(yy * NSX + lane) * CPAD + 2 * wrp] = __floats2half2_rn(a0, a1);
            if (lane < 2) {
                float b0 = (okY && pB) ? cr0[ro + colB] : 0.0f;
                float b1 = (okY && pB) ? cr1[ro + colB] : 0.0f;
                *(__half2*)&ns[(yy * NSX + 32 + lane) * CPAD + 2 * wrp] =
                    __floats2half2_rn(b0, b1);
            }
        }
        const int tnext = tile + GRID;
        if (t == 0 && tnext < NTILES) {
            const uint32_t bytes = 288u * row_bytes((tnext & 15) * 32);
            asm volatile("mbarrier.arrive.expect_tx.shared.b64 _, [%0], %1;"
                         :: "r"(mbar), "r"(bytes) : "memory");
        }
        __syncthreads();                 // ns ready, raw free, expect_tx visible

        // ---- prefetch next tile (hidden under compute + epilogue) ----
        if (tnext < NTILES)
            issue_tile_bulk(xin, sraw, mbar, tnext, ci, xb);

        // ---- compute: kw -> B frags -> xh -> 4 cached A frags -> 12 MMA ----
        float acc[4][2][4];
        #pragma unroll
        for (int i = 0; i < 4; ++i)
            #pragma unroll
            for (int nn = 0; nn < 2; ++nn)
                #pragma unroll
                for (int j = 0; j < 4; ++j) acc[i][nn][j] = 0.0f;

        #pragma unroll
        for (int kw = 0; kw < 3; ++kw) {
            uint32_t bf[3][2][2];
            #pragma unroll
            for (int dy = 0; dy < 3; ++dy)
                #pragma unroll
                for (int nn = 0; nn < 2; ++nn) {
                    uint2 v = Bs2[((dy * 3 + kw) * 2 + nn) * 32 + lane];
                    bf[dy][nn][0] = v.x;
                    bf[dy][nn][1] = v.y;
                }
            #pragma unroll
            for (int xh = 0; xh < 2; ++xh) {
                uint32_t F[4][4];
                #pragma unroll
                for (int q = 0; q < 4; ++q)
                    ldsm4(F[q][0], F[q][1], F[q][2], F[q][3],
                          fb + (uint32_t)(((2 * wrp + q) * NSX + xh * 16 + kw) * (CPAD * 2)));
                #pragma unroll
                for (int yl = 0; yl < 2; ++yl)
                    #pragma unroll
                    for (int dy = 0; dy < 3; ++dy) {
                        const int q = yl + dy;
                        const int i = yl * 2 + xh;
                        mma16816(acc[i][0], F[q][0], F[q][1], F[q][2], F[q][3],
                                 bf[dy][0][0], bf[dy][0][1]);
                        mma16816(acc[i][1], F[q][0], F[q][1], F[q][2], F[q][3],
                                 bf[dy][1][0], bf[dy][1][1]);
                    }
            }
        }

        // ---- direct-store epilogue ----
        #pragma unroll
        for (int i = 0; i < 4; ++i) {
            const int yloc = wrp * 2 + (i >> 1);
            const int xh   = i & 1;
            const int y  = y0 + yloc;
            const int xg = x0 + xh * 16 + g;
            #pragma unroll
            for (int nn = 0; nn < 2; ++nn) {
                const int co = nn * 8 + cq;
                float* op = out + ((size_t)(n * 16 + co) * HW + y) * HW + xg;
                op[0]                   = acc[i][nn][0];
                op[(size_t)HW * HW]     = acc[i][nn][1];
                op[8]                   = acc[i][nn][2];
                op[(size_t)HW * HW + 8] = acc[i][nn][3];
            }
        }
    }
}

extern "C" void kernel_launch(void* const* d_in, const int* in_sizes, int n_in,
                              void* d_out, int out_size) {
    const float* x = (const float*)d_in[0];   // [8,16,512,512]
    const float* w = (const float*)d_in[1];   // [16,144]
    float* out = (float*)d_out;

    static int attr_done = 0;
    if (!attr_done) {
        cudaFuncSetAttribute(conv_mma_bulk,
                             cudaFuncAttributeMaxDynamicSharedMemorySize, SM_TOTAL);
        attr_done = 1;
    }
    conv_mma_bulk<<<GRID, 256, SM_TOTAL>>>(x, w, out);
}